// round 15
// baseline (speedup 1.0000x reference)
#include <cuda_runtime.h>
#include <cuda_bf16.h>
#include <cstdint>

// GCN 2-layer: out = S(relu(S(x@W1)+b1) @ W2) + b2, S = D^-1/2 (A+I) D^-1/2
// hs = (x@W)*dinv[row]; agg init = hs (self loop); per edge agg[dst] += hs[src]
// via red.global.add.v4.f32; node epilogue applies dinv[dst] + bias.
// ALL scratch buffers are __device__ globals referenced ONLY from device code
// (passing a __device__ symbol as a host-side kernel arg is invalid CUDA and
// was the cause of the rel_err=1.0 failures).

#define NMAX 100352  // 100000 rounded up

__device__ __align__(16) float g_dinv[NMAX];
__device__ __align__(16) float g_hs1[(size_t)NMAX * 128];   // reused as x1 post-relu
__device__ __align__(16) float g_agg1[(size_t)NMAX * 128];
__device__ __align__(16) float g_hs2[(size_t)NMAX * 64];
__device__ __align__(16) float g_agg2[(size_t)NMAX * 64];

// ---------------- degree / dinv ----------------
__global__ void k_deg_init(int n) {
    int i = blockIdx.x * blockDim.x + threadIdx.x;
    if (i < n) g_dinv[i] = 1.0f;  // self-loop contributes 1
}

__global__ void k_deg_acc(const int* __restrict__ dst, int e) {
    int i = blockIdx.x * blockDim.x + threadIdx.x;
    if (i < e) atomicAdd(&g_dinv[dst[i]], 1.0f);
}

__global__ void k_rsqrt(int n) {
    int i = blockIdx.x * blockDim.x + threadIdx.x;
    if (i < n) g_dinv[i] = rsqrtf(g_dinv[i]);
}

// ---------------- GEMM: hs = (A @ W) * dinv[row]; agg = hs ----------------
// LAYER=1: A=x (param), BN=128 -> g_hs1/g_agg1.  LAYER=2: A=g_hs1, BN=64 -> g_hs2/g_agg2.
template <int LAYER>
__global__ void __launch_bounds__(256)
k_gemm_scale(const float* __restrict__ Ain, const float* __restrict__ W, int M) {
    constexpr int BN = (LAYER == 1) ? 128 : 64;
    constexpr int TN = (LAYER == 1) ? 8 : 4;
    constexpr int BM = 128, BK = 8, TM = 8, K = 128;

    const float* A = (LAYER == 1) ? Ain : g_hs1;
    float* hs  = (LAYER == 1) ? g_hs1  : g_hs2;
    float* agg = (LAYER == 1) ? g_agg1 : g_agg2;

    __shared__ float As[BK][BM];
    __shared__ float Ws[BK][BN];

    const int tid = threadIdx.x;
    const int tn = tid % (BN / TN);
    const int tm = tid / (BN / TN);
    const int rowBase = blockIdx.x * BM;

    const int arow = tid >> 1;
    const int acol = (tid & 1) * 4;
    constexpr int WL4 = BK * BN / 4;
    const int wrow = tid / (BN / 4);
    const int wcol = (tid % (BN / 4)) * 4;

    float acc[TM][TN];
#pragma unroll
    for (int i = 0; i < TM; i++)
#pragma unroll
        for (int j = 0; j < TN; j++) acc[i][j] = 0.0f;

    for (int k0 = 0; k0 < K; k0 += BK) {
        {
            int gr = rowBase + arow;
            float4 v = make_float4(0.f, 0.f, 0.f, 0.f);
            if (gr < M)
                v = *reinterpret_cast<const float4*>(A + (size_t)gr * K + k0 + acol);
            As[acol + 0][arow] = v.x;
            As[acol + 1][arow] = v.y;
            As[acol + 2][arow] = v.z;
            As[acol + 3][arow] = v.w;
        }
        if (tid < WL4) {
            float4 v = *reinterpret_cast<const float4*>(W + (size_t)(k0 + wrow) * BN + wcol);
            *reinterpret_cast<float4*>(&Ws[wrow][wcol]) = v;
        }
        __syncthreads();

#pragma unroll
        for (int k = 0; k < BK; k++) {
            float rm[TM], rn[TN];
#pragma unroll
            for (int i = 0; i < TM; i++) rm[i] = As[k][tm * TM + i];
#pragma unroll
            for (int j = 0; j < TN; j++) rn[j] = Ws[k][tn * TN + j];
#pragma unroll
            for (int i = 0; i < TM; i++)
#pragma unroll
                for (int j = 0; j < TN; j++) acc[i][j] += rm[i] * rn[j];
        }
        __syncthreads();
    }

#pragma unroll
    for (int i = 0; i < TM; i++) {
        int gr = rowBase + tm * TM + i;
        if (gr >= M) continue;
        float s = g_dinv[gr];
#pragma unroll
        for (int j = 0; j < TN; j += 4) {
            float4 v;
            v.x = acc[i][j + 0] * s;
            v.y = acc[i][j + 1] * s;
            v.z = acc[i][j + 2] * s;
            v.w = acc[i][j + 3] * s;
            size_t idx = (size_t)gr * BN + tn * TN + j;
            *reinterpret_cast<float4*>(hs + idx) = v;
            *reinterpret_cast<float4*>(agg + idx) = v;
        }
    }
}

// ---------------- edge scatter ----------------
__device__ __forceinline__ void red_add_v4(float* p, float4 v) {
    asm volatile("red.global.add.v4.f32 [%0], {%1,%2,%3,%4};" ::"l"(p), "f"(v.x),
                 "f"(v.y), "f"(v.z), "f"(v.w)
                 : "memory");
}

// 128 floats per edge: one warp per edge, float4 per lane
__global__ void k_scatter128(const int* __restrict__ src, const int* __restrict__ dst,
                             int e) {
    int warp = (blockIdx.x * blockDim.x + threadIdx.x) >> 5;
    int lane = threadIdx.x & 31;
    if (warp >= e) return;
    int s = __ldg(&src[warp]);
    int d = __ldg(&dst[warp]);
    float4 v = reinterpret_cast<const float4*>(g_hs1 + (size_t)s * 128)[lane];
    red_add_v4(g_agg1 + (size_t)d * 128 + lane * 4, v);
}

// 64 floats per edge: half-warp per edge, float4 per lane
__global__ void k_scatter64(const int* __restrict__ src, const int* __restrict__ dst,
                            int e) {
    int t = blockIdx.x * blockDim.x + threadIdx.x;
    int edge = t >> 4;
    int l = t & 15;
    if (edge >= e) return;
    int s = __ldg(&src[edge]);
    int d = __ldg(&dst[edge]);
    float4 v = reinterpret_cast<const float4*>(g_hs2 + (size_t)s * 64)[l];
    red_add_v4(g_agg2 + (size_t)d * 64 + l * 4, v);
}

// ---------------- node epilogues ----------------
// x1 = relu(dinv*agg1 + b1), written into g_hs1 (reused)
__global__ void k_relu_bias(const float* __restrict__ b1, int M) {
    int idx = blockIdx.x * blockDim.x + threadIdx.x;  // float4 index over M*32
    if (idx >= M * 32) return;
    int row = idx >> 5;
    int q = idx & 31;
    float s = g_dinv[row];
    float4 a = reinterpret_cast<const float4*>(g_agg1)[idx];
    float4 b = reinterpret_cast<const float4*>(b1)[q];
    float4 r;
    r.x = fmaxf(fmaf(s, a.x, b.x), 0.f);
    r.y = fmaxf(fmaf(s, a.y, b.y), 0.f);
    r.z = fmaxf(fmaf(s, a.z, b.z), 0.f);
    r.w = fmaxf(fmaf(s, a.w, b.w), 0.f);
    reinterpret_cast<float4*>(g_hs1)[idx] = r;
}

// out = dinv*agg2 + b2
__global__ void k_final(const float* __restrict__ b2, float* __restrict__ out, int M) {
    int idx = blockIdx.x * blockDim.x + threadIdx.x;  // float4 index over M*16
    if (idx >= M * 16) return;
    int row = idx >> 4;
    int q = idx & 15;
    float s = g_dinv[row];
    float4 a = reinterpret_cast<const float4*>(g_agg2)[idx];
    float4 b = reinterpret_cast<const float4*>(b2)[q];
    float4 r;
    r.x = fmaf(s, a.x, b.x);
    r.y = fmaf(s, a.y, b.y);
    r.z = fmaf(s, a.z, b.z);
    r.w = fmaf(s, a.w, b.w);
    reinterpret_cast<float4*>(out)[idx] = r;
}

extern "C" void kernel_launch(void* const* d_in, const int* in_sizes, int n_in,
                              void* d_out, int out_size) {
    // ---- bind inputs by element count (robust to metadata ordering) ----
    const float* x  = nullptr;
    const int*   ei = nullptr;
    const float* W1 = nullptr;
    const float* b1 = nullptr;
    const float* W2 = nullptr;
    const float* b2 = nullptr;
    int x_sz = 0, ei_sz = 0;

    const void* bigp[2] = {nullptr, nullptr};
    int bigsz[2] = {0, 0};
    int nbig = 0;

    for (int i = 0; i < n_in; i++) {
        int sz = in_sizes[i];
        const void* p = d_in[i];
        if (sz == 16384)      W1 = (const float*)p;   // 128*128
        else if (sz == 8192)  W2 = (const float*)p;   // 128*64
        else if (sz == 128)   b1 = (const float*)p;
        else if (sz == 64)    b2 = (const float*)p;
        else if (sz > 1000000 && nbig < 2) {
            bigp[nbig] = p; bigsz[nbig] = sz; nbig++;
        }
    }
    if (nbig == 2) {
        int xi = (bigsz[0] >= bigsz[1]) ? 0 : 1;  // larger = x (N*128 > 2*E)
        x  = (const float*)bigp[xi];     x_sz  = bigsz[xi];
        ei = (const int*)bigp[1 - xi];   ei_sz = bigsz[1 - xi];
    }
    // fallback: assume reference positional order (x, edge_index, W1, b1, W2, b2)
    if ((!x || !ei || !W1 || !W2 || !b1 || !b2) && n_in >= 6) {
        x  = (const float*)d_in[0]; x_sz  = in_sizes[0];
        ei = (const int*)d_in[1];   ei_sz = in_sizes[1];
        W1 = (const float*)d_in[2];
        b1 = (const float*)d_in[3];
        W2 = (const float*)d_in[4];
        b2 = (const float*)d_in[5];
    }

    float* out = (float*)d_out;
    const int M = x_sz / 128;   // nodes
    const int E = ei_sz / 2;    // edges
    const int* src = ei;
    const int* dst = ei + E;

    const int T = 256;
    // degree -> dinv
    k_deg_init<<<(M + T - 1) / T, T>>>(M);
    k_deg_acc<<<(E + T - 1) / T, T>>>(dst, E);
    k_rsqrt<<<(M + T - 1) / T, T>>>(M);

    // layer 1
    int gblk = (M + 127) / 128;
    k_gemm_scale<1><<<gblk, 256>>>(x, W1, M);
    {
        int blocks = (E * 32 + T - 1) / T;   // 1 warp / edge
        k_scatter128<<<blocks, T>>>(src, dst, E);
    }
    k_relu_bias<<<(M * 32 + T - 1) / T, T>>>(b1, M);

    // layer 2 (Ain unused for LAYER=2; reads g_hs1 internally)
    k_gemm_scale<2><<<gblk, 256>>>(x, W2, M);
    {
        int blocks = (E * 16 + T - 1) / T;   // half-warp / edge
        k_scatter64<<<blocks, T>>>(src, dst, E);
    }
    k_final<<<(M * 16 + T - 1) / T, T>>>(b2, out, M);
}

// round 16
// speedup vs baseline: 1.6609x; 1.6609x over previous
#include <cuda_runtime.h>
#include <cuda_bf16.h>
#include <cstdint>

// GCN 2-layer, CSR-gather formulation (no float atomics):
//   hs = (x@W)*dinv[row]
//   x1[d] = relu(dinv[d]*(hs1[d] + sum_{e: dst=d} hs1[src_e]) + b1)
//   out[d] =      dinv[d]*(hs2[d] + sum_{e: dst=d} hs2[src_e]) + b2
// CSR built per launch: histogram(dst) -> block scan -> bin src by dst.

#define NMAX 100352          // >= 100000
#define EMAX 1800000         // >= 1.6M edges
#define NBMAX 128            // >= NMAX/1024

__device__ __align__(16) float g_dinv[NMAX];
__device__ __align__(16) float g_hs1[(size_t)NMAX * 128];
__device__ __align__(16) float g_x1 [(size_t)NMAX * 128];
__device__ __align__(16) float g_hs2[(size_t)NMAX * 64];
__device__ int g_cnt[NMAX];
__device__ int g_rowstart[NMAX];
__device__ int g_cursor[NMAX];
__device__ int g_esrc[EMAX];
__device__ int g_bsum[NBMAX];
__device__ int g_boff[NBMAX];

// ---------------- CSR build ----------------
__global__ void k_zero_cnt(int n) {
    int i = blockIdx.x * blockDim.x + threadIdx.x;
    if (i < n) g_cnt[i] = 0;
}

__global__ void k_hist(const int* __restrict__ dst, int e) {
    int i = blockIdx.x * blockDim.x + threadIdx.x;
    if (i < e) atomicAdd(&g_cnt[dst[i]], 1);
}

// per-1024-chunk sums (256 threads x 4 elems)
__global__ void k_blocksum(int n) {
    __shared__ int sm[256];
    int tid = threadIdx.x;
    int base = blockIdx.x * 1024 + tid * 4;
    int s = 0;
#pragma unroll
    for (int i = 0; i < 4; i++) {
        int idx = base + i;
        if (idx < n) s += g_cnt[idx];
    }
    sm[tid] = s;
    __syncthreads();
    for (int off = 128; off > 0; off >>= 1) {
        if (tid < off) sm[tid] += sm[tid + off];
        __syncthreads();
    }
    if (tid == 0) g_bsum[blockIdx.x] = sm[0];
}

// serial exclusive scan over chunk sums (<=128 values)
__global__ void k_scan_bsum(int nb) {
    if (threadIdx.x == 0 && blockIdx.x == 0) {
        int run = 0;
        for (int b = 0; b < nb; b++) {
            int t = g_bsum[b];
            g_boff[b] = run;
            run += t;
        }
    }
}

// in-chunk exclusive scan + write row_start/cursor; also dinv = rsqrt(1+deg)
__global__ void k_scan_rows(int n) {
    __shared__ int ts[256];
    int tid = threadIdx.x;
    int base = blockIdx.x * 1024 + tid * 4;
    int v[4];
    int sum = 0;
#pragma unroll
    for (int i = 0; i < 4; i++) {
        int idx = base + i;
        v[i] = (idx < n) ? g_cnt[idx] : 0;
        sum += v[i];
    }
    ts[tid] = sum;
    __syncthreads();
    // Hillis-Steele inclusive scan over 256 thread sums
    for (int off = 1; off < 256; off <<= 1) {
        int t = (tid >= off) ? ts[tid - off] : 0;
        __syncthreads();
        ts[tid] += t;
        __syncthreads();
    }
    int run = g_boff[blockIdx.x] + ts[tid] - sum;  // exclusive offset
#pragma unroll
    for (int i = 0; i < 4; i++) {
        int idx = base + i;
        if (idx < n) {
            g_rowstart[idx] = run;
            g_cursor[idx] = run;
            g_dinv[idx] = rsqrtf(1.0f + (float)v[i]);
            run += v[i];
        }
    }
}

__global__ void k_bin(const int* __restrict__ src, const int* __restrict__ dst, int e) {
    int i = blockIdx.x * blockDim.x + threadIdx.x;
    if (i >= e) return;
    int d = dst[i];
    int pos = atomicAdd(&g_cursor[d], 1);
    g_esrc[pos] = src[i];
}

// ---------------- GEMM: hs = (A @ W) * dinv[row] ----------------
// LAYER=1: A=x (param), BN=128 -> g_hs1.  LAYER=2: A=g_x1, BN=64 -> g_hs2.
template <int LAYER>
__global__ void __launch_bounds__(256)
k_gemm_scale(const float* __restrict__ Ain, const float* __restrict__ W, int M) {
    constexpr int BN = (LAYER == 1) ? 128 : 64;
    constexpr int TN = (LAYER == 1) ? 8 : 4;
    constexpr int BM = 128, BK = 8, TM = 8, K = 128;

    const float* A = (LAYER == 1) ? Ain : g_x1;
    float* hs = (LAYER == 1) ? g_hs1 : g_hs2;

    __shared__ float As[BK][BM];
    __shared__ float Ws[BK][BN];

    const int tid = threadIdx.x;
    const int tn = tid % (BN / TN);
    const int tm = tid / (BN / TN);
    const int rowBase = blockIdx.x * BM;

    const int arow = tid >> 1;
    const int acol = (tid & 1) * 4;
    constexpr int WL4 = BK * BN / 4;
    const int wrow = tid / (BN / 4);
    const int wcol = (tid % (BN / 4)) * 4;

    float acc[TM][TN];
#pragma unroll
    for (int i = 0; i < TM; i++)
#pragma unroll
        for (int j = 0; j < TN; j++) acc[i][j] = 0.0f;

    for (int k0 = 0; k0 < K; k0 += BK) {
        {
            int gr = rowBase + arow;
            float4 v = make_float4(0.f, 0.f, 0.f, 0.f);
            if (gr < M)
                v = *reinterpret_cast<const float4*>(A + (size_t)gr * K + k0 + acol);
            As[acol + 0][arow] = v.x;
            As[acol + 1][arow] = v.y;
            As[acol + 2][arow] = v.z;
            As[acol + 3][arow] = v.w;
        }
        if (tid < WL4) {
            float4 v = *reinterpret_cast<const float4*>(W + (size_t)(k0 + wrow) * BN + wcol);
            *reinterpret_cast<float4*>(&Ws[wrow][wcol]) = v;
        }
        __syncthreads();

#pragma unroll
        for (int k = 0; k < BK; k++) {
            float rm[TM], rn[TN];
#pragma unroll
            for (int i = 0; i < TM; i++) rm[i] = As[k][tm * TM + i];
#pragma unroll
            for (int j = 0; j < TN; j++) rn[j] = Ws[k][tn * TN + j];
#pragma unroll
            for (int i = 0; i < TM; i++)
#pragma unroll
                for (int j = 0; j < TN; j++) acc[i][j] += rm[i] * rn[j];
        }
        __syncthreads();
    }

#pragma unroll
    for (int i = 0; i < TM; i++) {
        int gr = rowBase + tm * TM + i;
        if (gr >= M) continue;
        float s = g_dinv[gr];
#pragma unroll
        for (int j = 0; j < TN; j += 4) {
            float4 v;
            v.x = acc[i][j + 0] * s;
            v.y = acc[i][j + 1] * s;
            v.z = acc[i][j + 2] * s;
            v.w = acc[i][j + 3] * s;
            *reinterpret_cast<float4*>(hs + (size_t)gr * BN + tn * TN + j) = v;
        }
    }
}

// ---------------- CSR gather (fused epilogue) ----------------
// layer 1: one warp per dst node, lane = float4 of the 128-wide row; relu+bias
__global__ void k_gather128(const float* __restrict__ b1, int n) {
    int warp = (blockIdx.x * blockDim.x + threadIdx.x) >> 5;
    int lane = threadIdx.x & 31;
    if (warp >= n) return;
    int d = warp;
    float4 acc = reinterpret_cast<const float4*>(g_hs1 + (size_t)d * 128)[lane];
    float4 acc2 = make_float4(0.f, 0.f, 0.f, 0.f);
    int beg = g_rowstart[d];
    int deg = g_cnt[d];
    int j = 0;
    for (; j + 1 < deg; j += 2) {
        int s0 = __ldg(&g_esrc[beg + j]);
        int s1 = __ldg(&g_esrc[beg + j + 1]);
        float4 v0 = reinterpret_cast<const float4*>(g_hs1 + (size_t)s0 * 128)[lane];
        float4 v1 = reinterpret_cast<const float4*>(g_hs1 + (size_t)s1 * 128)[lane];
        acc.x += v0.x; acc.y += v0.y; acc.z += v0.z; acc.w += v0.w;
        acc2.x += v1.x; acc2.y += v1.y; acc2.z += v1.z; acc2.w += v1.w;
    }
    if (j < deg) {
        int s0 = __ldg(&g_esrc[beg + j]);
        float4 v0 = reinterpret_cast<const float4*>(g_hs1 + (size_t)s0 * 128)[lane];
        acc.x += v0.x; acc.y += v0.y; acc.z += v0.z; acc.w += v0.w;
    }
    acc.x += acc2.x; acc.y += acc2.y; acc.z += acc2.z; acc.w += acc2.w;
    float sc = g_dinv[d];
    float4 bb = reinterpret_cast<const float4*>(b1)[lane];
    float4 r;
    r.x = fmaxf(fmaf(sc, acc.x, bb.x), 0.f);
    r.y = fmaxf(fmaf(sc, acc.y, bb.y), 0.f);
    r.z = fmaxf(fmaf(sc, acc.z, bb.z), 0.f);
    r.w = fmaxf(fmaf(sc, acc.w, bb.w), 0.f);
    reinterpret_cast<float4*>(g_x1 + (size_t)d * 128)[lane] = r;
}

// layer 2: one warp per dst node, lane = float2 of the 64-wide row; writes out
__global__ void k_gather64(const float* __restrict__ b2, float* __restrict__ out, int n) {
    int warp = (blockIdx.x * blockDim.x + threadIdx.x) >> 5;
    int lane = threadIdx.x & 31;
    if (warp >= n) return;
    int d = warp;
    float2 acc = reinterpret_cast<const float2*>(g_hs2 + (size_t)d * 64)[lane];
    float2 acc2 = make_float2(0.f, 0.f);
    int beg = g_rowstart[d];
    int deg = g_cnt[d];
    int j = 0;
    for (; j + 1 < deg; j += 2) {
        int s0 = __ldg(&g_esrc[beg + j]);
        int s1 = __ldg(&g_esrc[beg + j + 1]);
        float2 v0 = reinterpret_cast<const float2*>(g_hs2 + (size_t)s0 * 64)[lane];
        float2 v1 = reinterpret_cast<const float2*>(g_hs2 + (size_t)s1 * 64)[lane];
        acc.x += v0.x; acc.y += v0.y;
        acc2.x += v1.x; acc2.y += v1.y;
    }
    if (j < deg) {
        int s0 = __ldg(&g_esrc[beg + j]);
        float2 v0 = reinterpret_cast<const float2*>(g_hs2 + (size_t)s0 * 64)[lane];
        acc.x += v0.x; acc.y += v0.y;
    }
    acc.x += acc2.x; acc.y += acc2.y;
    float sc = g_dinv[d];
    float2 bb = reinterpret_cast<const float2*>(b2)[lane];
    float2 r;
    r.x = fmaf(sc, acc.x, bb.x);
    r.y = fmaf(sc, acc.y, bb.y);
    reinterpret_cast<float2*>(out + (size_t)d * 64)[lane] = r;
}

extern "C" void kernel_launch(void* const* d_in, const int* in_sizes, int n_in,
                              void* d_out, int out_size) {
    // ---- bind inputs by element count (robust to metadata ordering) ----
    const float* x = nullptr;
    const int* ei = nullptr;
    const float* W1 = nullptr;
    const float* b1 = nullptr;
    const float* W2 = nullptr;
    const float* b2 = nullptr;
    int x_sz = 0, ei_sz = 0;

    const void* bigp[2] = {nullptr, nullptr};
    int bigsz[2] = {0, 0};
    int nbig = 0;

    for (int i = 0; i < n_in; i++) {
        int sz = in_sizes[i];
        const void* p = d_in[i];
        if (sz == 16384)      W1 = (const float*)p;
        else if (sz == 8192)  W2 = (const float*)p;
        else if (sz == 128)   b1 = (const float*)p;
        else if (sz == 64)    b2 = (const float*)p;
        else if (sz > 1000000 && nbig < 2) {
            bigp[nbig] = p; bigsz[nbig] = sz; nbig++;
        }
    }
    if (nbig == 2) {
        int xi = (bigsz[0] >= bigsz[1]) ? 0 : 1;
        x = (const float*)bigp[xi];    x_sz = bigsz[xi];
        ei = (const int*)bigp[1 - xi]; ei_sz = bigsz[1 - xi];
    }
    if ((!x || !ei || !W1 || !W2 || !b1 || !b2) && n_in >= 6) {
        x = (const float*)d_in[0];  x_sz = in_sizes[0];
        ei = (const int*)d_in[1];   ei_sz = in_sizes[1];
        W1 = (const float*)d_in[2];
        b1 = (const float*)d_in[3];
        W2 = (const float*)d_in[4];
        b2 = (const float*)d_in[5];
    }

    float* out = (float*)d_out;
    const int M = x_sz / 128;  // nodes
    const int E = ei_sz / 2;   // edges
    const int* src = ei;
    const int* dst = ei + E;

    const int T = 256;
    const int NB = (M + 1023) / 1024;

    // CSR build + dinv
    k_zero_cnt<<<(M + T - 1) / T, T>>>(M);
    k_hist<<<(E + T - 1) / T, T>>>(dst, E);
    k_blocksum<<<NB, 256>>>(M);
    k_scan_bsum<<<1, 32>>>(NB);
    k_scan_rows<<<NB, 256>>>(M);
    k_bin<<<(E + T - 1) / T, T>>>(src, dst, E);

    // layer 1
    int gblk = (M + 127) / 128;
    k_gemm_scale<1><<<gblk, 256>>>(x, W1, M);
    k_gather128<<<(M * 32 + T - 1) / T, T>>>(b1, M);

    // layer 2
    k_gemm_scale<2><<<gblk, 256>>>(x, W2, M);
    k_gather64<<<(M * 32 + T - 1) / T, T>>>(b2, out, M);
}

// round 17
// speedup vs baseline: 1.6961x; 1.0212x over previous
#include <cuda_runtime.h>
#include <cuda_bf16.h>
#include <cstdint>

// GCN 2-layer, CSR-gather formulation (no float atomics):
//   hs = (x@W)*dinv[row]
//   x1[d] = relu(dinv[d]*(hs1[d] + sum_{e: dst=d} hs1[src_e]) + b1)
//   out[d] =      dinv[d]*(hs2[d] + sum_{e: dst=d} hs2[src_e]) + b2
// CSR per launch: histogram(dst) -> atomic chunk allocation (no prefix scan;
// row-chunk order is arbitrary, which is fine) -> bin src by dst.

#define NMAX 100352          // >= 100000
#define EMAX 1800000         // >= 1.6M edges

__device__ __align__(16) float g_dinv[NMAX];
__device__ __align__(16) float g_hs1[(size_t)NMAX * 128];
__device__ __align__(16) float g_x1 [(size_t)NMAX * 128];
__device__ __align__(16) float g_hs2[(size_t)NMAX * 64];
__device__ int g_cnt[NMAX];
__device__ int g_rowstart[NMAX];
__device__ int g_cursor[NMAX];
__device__ int g_esrc[EMAX];
__device__ int g_total;

// ---------------- CSR build ----------------
__global__ void k_zero_cnt(int n) {
    int i = blockIdx.x * blockDim.x + threadIdx.x;
    if (i < n) g_cnt[i] = 0;
    if (i == 0) g_total = 0;
}

__global__ void k_hist(const int* __restrict__ dst, int e) {
    int i = blockIdx.x * blockDim.x + threadIdx.x;
    if (i < e) atomicAdd(&g_cnt[dst[i]], 1);
}

// Allocate each row a contiguous chunk via one global atomic; also dinv.
__global__ void k_alloc(int n) {
    int i = blockIdx.x * blockDim.x + threadIdx.x;
    if (i >= n) return;
    int c = g_cnt[i];
    int pos = atomicAdd(&g_total, c);
    g_rowstart[i] = pos;
    g_cursor[i] = pos;
    g_dinv[i] = rsqrtf(1.0f + (float)c);
}

__global__ void k_bin(const int* __restrict__ src, const int* __restrict__ dst, int e) {
    int i = blockIdx.x * blockDim.x + threadIdx.x;
    if (i >= e) return;
    int d = dst[i];
    int pos = atomicAdd(&g_cursor[d], 1);
    g_esrc[pos] = src[i];
}

// ---------------- GEMM: hs = (A @ W) * dinv[row] ----------------
// LAYER=1: A=x (param), BN=128 -> g_hs1.  LAYER=2: A=g_x1, BN=64 -> g_hs2.
// Inner loop uses LDS.128 register-tile loads (As/Ws rows contiguous, 16B aligned).
template <int LAYER>
__global__ void __launch_bounds__(256)
k_gemm_scale(const float* __restrict__ Ain, const float* __restrict__ W, int M) {
    constexpr int BN = (LAYER == 1) ? 128 : 64;
    constexpr int TN = (LAYER == 1) ? 8 : 4;
    constexpr int BM = 128, BK = 8, TM = 8, K = 128;

    const float* A = (LAYER == 1) ? Ain : g_x1;
    float* hs = (LAYER == 1) ? g_hs1 : g_hs2;

    __shared__ __align__(16) float As[BK][BM];
    __shared__ __align__(16) float Ws[BK][BN];

    const int tid = threadIdx.x;
    const int tn = tid % (BN / TN);
    const int tm = tid / (BN / TN);
    const int rowBase = blockIdx.x * BM;

    const int arow = tid >> 1;
    const int acol = (tid & 1) * 4;
    constexpr int WL4 = BK * BN / 4;
    const int wrow = tid / (BN / 4);
    const int wcol = (tid % (BN / 4)) * 4;

    float acc[TM][TN];
#pragma unroll
    for (int i = 0; i < TM; i++)
#pragma unroll
        for (int j = 0; j < TN; j++) acc[i][j] = 0.0f;

    for (int k0 = 0; k0 < K; k0 += BK) {
        {
            int gr = rowBase + arow;
            float4 v = make_float4(0.f, 0.f, 0.f, 0.f);
            if (gr < M)
                v = *reinterpret_cast<const float4*>(A + (size_t)gr * K + k0 + acol);
            As[acol + 0][arow] = v.x;
            As[acol + 1][arow] = v.y;
            As[acol + 2][arow] = v.z;
            As[acol + 3][arow] = v.w;
        }
        if (tid < WL4) {
            float4 v = *reinterpret_cast<const float4*>(W + (size_t)(k0 + wrow) * BN + wcol);
            *reinterpret_cast<float4*>(&Ws[wrow][wcol]) = v;
        }
        __syncthreads();

#pragma unroll
        for (int k = 0; k < BK; k++) {
            float4 a0 = *reinterpret_cast<const float4*>(&As[k][tm * TM]);
            float4 a1 = *reinterpret_cast<const float4*>(&As[k][tm * TM + 4]);
            float rm[TM] = {a0.x, a0.y, a0.z, a0.w, a1.x, a1.y, a1.z, a1.w};
            float rn[TN];
            if (TN == 8) {
                float4 w0 = *reinterpret_cast<const float4*>(&Ws[k][tn * TN]);
                float4 w1 = *reinterpret_cast<const float4*>(&Ws[k][tn * TN + 4]);
                rn[0] = w0.x; rn[1] = w0.y; rn[2] = w0.z; rn[3] = w0.w;
                rn[4] = w1.x; rn[5] = w1.y; rn[6] = w1.z; rn[7] = w1.w;
            } else {
                float4 w0 = *reinterpret_cast<const float4*>(&Ws[k][tn * TN]);
                rn[0] = w0.x; rn[1] = w0.y; rn[2] = w0.z; rn[3] = w0.w;
            }
#pragma unroll
            for (int i = 0; i < TM; i++)
#pragma unroll
                for (int j = 0; j < TN; j++) acc[i][j] += rm[i] * rn[j];
        }
        __syncthreads();
    }

#pragma unroll
    for (int i = 0; i < TM; i++) {
        int gr = rowBase + tm * TM + i;
        if (gr >= M) continue;
        float s = g_dinv[gr];
#pragma unroll
        for (int j = 0; j < TN; j += 4) {
            float4 v;
            v.x = acc[i][j + 0] * s;
            v.y = acc[i][j + 1] * s;
            v.z = acc[i][j + 2] * s;
            v.w = acc[i][j + 3] * s;
            *reinterpret_cast<float4*>(hs + (size_t)gr * BN + tn * TN + j) = v;
        }
    }
}

// ---------------- CSR gather (fused epilogue) ----------------
// layer 1: one warp per dst node, lane = float4 of the 128-wide row; relu+bias
__global__ void k_gather128(const float* __restrict__ b1, int n) {
    int warp = (blockIdx.x * blockDim.x + threadIdx.x) >> 5;
    int lane = threadIdx.x & 31;
    if (warp >= n) return;
    int d = warp;
    float4 acc = reinterpret_cast<const float4*>(g_hs1 + (size_t)d * 128)[lane];
    float4 acc2 = make_float4(0.f, 0.f, 0.f, 0.f);
    int beg = g_rowstart[d];
    int deg = g_cnt[d];
    int j = 0;
    for (; j + 1 < deg; j += 2) {
        int s0 = __ldg(&g_esrc[beg + j]);
        int s1 = __ldg(&g_esrc[beg + j + 1]);
        float4 v0 = reinterpret_cast<const float4*>(g_hs1 + (size_t)s0 * 128)[lane];
        float4 v1 = reinterpret_cast<const float4*>(g_hs1 + (size_t)s1 * 128)[lane];
        acc.x += v0.x; acc.y += v0.y; acc.z += v0.z; acc.w += v0.w;
        acc2.x += v1.x; acc2.y += v1.y; acc2.z += v1.z; acc2.w += v1.w;
    }
    if (j < deg) {
        int s0 = __ldg(&g_esrc[beg + j]);
        float4 v0 = reinterpret_cast<const float4*>(g_hs1 + (size_t)s0 * 128)[lane];
        acc.x += v0.x; acc.y += v0.y; acc.z += v0.z; acc.w += v0.w;
    }
    acc.x += acc2.x; acc.y += acc2.y; acc.z += acc2.z; acc.w += acc2.w;
    float sc = g_dinv[d];
    float4 bb = reinterpret_cast<const float4*>(b1)[lane];
    float4 r;
    r.x = fmaxf(fmaf(sc, acc.x, bb.x), 0.f);
    r.y = fmaxf(fmaf(sc, acc.y, bb.y), 0.f);
    r.z = fmaxf(fmaf(sc, acc.z, bb.z), 0.f);
    r.w = fmaxf(fmaf(sc, acc.w, bb.w), 0.f);
    reinterpret_cast<float4*>(g_x1 + (size_t)d * 128)[lane] = r;
}

// layer 2: one warp per dst node, lane = float2 of the 64-wide row; writes out
__global__ void k_gather64(const float* __restrict__ b2, float* __restrict__ out, int n) {
    int warp = (blockIdx.x * blockDim.x + threadIdx.x) >> 5;
    int lane = threadIdx.x & 31;
    if (warp >= n) return;
    int d = warp;
    float2 acc = reinterpret_cast<const float2*>(g_hs2 + (size_t)d * 64)[lane];
    float2 acc2 = make_float2(0.f, 0.f);
    int beg = g_rowstart[d];
    int deg = g_cnt[d];
    int j = 0;
    for (; j + 1 < deg; j += 2) {
        int s0 = __ldg(&g_esrc[beg + j]);
        int s1 = __ldg(&g_esrc[beg + j + 1]);
        float2 v0 = reinterpret_cast<const float2*>(g_hs2 + (size_t)s0 * 64)[lane];
        float2 v1 = reinterpret_cast<const float2*>(g_hs2 + (size_t)s1 * 64)[lane];
        acc.x += v0.x; acc.y += v0.y;
        acc2.x += v1.x; acc2.y += v1.y;
    }
    if (j < deg) {
        int s0 = __ldg(&g_esrc[beg + j]);
        float2 v0 = reinterpret_cast<const float2*>(g_hs2 + (size_t)s0 * 64)[lane];
        acc.x += v0.x; acc.y += v0.y;
    }
    acc.x += acc2.x; acc.y += acc2.y;
    float sc = g_dinv[d];
    float2 bb = reinterpret_cast<const float2*>(b2)[lane];
    float2 r;
    r.x = fmaf(sc, acc.x, bb.x);
    r.y = fmaf(sc, acc.y, bb.y);
    reinterpret_cast<float2*>(out + (size_t)d * 64)[lane] = r;
}

extern "C" void kernel_launch(void* const* d_in, const int* in_sizes, int n_in,
                              void* d_out, int out_size) {
    // ---- bind inputs by element count (robust to metadata ordering) ----
    const float* x = nullptr;
    const int* ei = nullptr;
    const float* W1 = nullptr;
    const float* b1 = nullptr;
    const float* W2 = nullptr;
    const float* b2 = nullptr;
    int x_sz = 0, ei_sz = 0;

    const void* bigp[2] = {nullptr, nullptr};
    int bigsz[2] = {0, 0};
    int nbig = 0;

    for (int i = 0; i < n_in; i++) {
        int sz = in_sizes[i];
        const void* p = d_in[i];
        if (sz == 16384)      W1 = (const float*)p;
        else if (sz == 8192)  W2 = (const float*)p;
        else if (sz == 128)   b1 = (const float*)p;
        else if (sz == 64)    b2 = (const float*)p;
        else if (sz > 1000000 && nbig < 2) {
            bigp[nbig] = p; bigsz[nbig] = sz; nbig++;
        }
    }
    if (nbig == 2) {
        int xi = (bigsz[0] >= bigsz[1]) ? 0 : 1;
        x = (const float*)bigp[xi];    x_sz = bigsz[xi];
        ei = (const int*)bigp[1 - xi]; ei_sz = bigsz[1 - xi];
    }
    if ((!x || !ei || !W1 || !W2 || !b1 || !b2) && n_in >= 6) {
        x = (const float*)d_in[0];  x_sz = in_sizes[0];
        ei = (const int*)d_in[1];   ei_sz = in_sizes[1];
        W1 = (const float*)d_in[2];
        b1 = (const float*)d_in[3];
        W2 = (const float*)d_in[4];
        b2 = (const float*)d_in[5];
    }

    float* out = (float*)d_out;
    const int M = x_sz / 128;  // nodes
    const int E = ei_sz / 2;   // edges
    const int* src = ei;
    const int* dst = ei + E;

    const int T = 256;

    // CSR build + dinv
    k_zero_cnt<<<(M + T - 1) / T, T>>>(M);
    k_hist<<<(E + T - 1) / T, T>>>(dst, E);
    k_alloc<<<(M + T - 1) / T, T>>>(M);
    k_bin<<<(E + T - 1) / T, T>>>(src, dst, E);

    // layer 1
    int gblk = (M + 127) / 128;
    k_gemm_scale<1><<<gblk, 256>>>(x, W1, M);
    k_gather128<<<(M * 32 + T - 1) / T, T>>>(b1, M);

    // layer 2
    k_gemm_scale<2><<<gblk, 256>>>(x, W2, M);
    k_gather64<<<(M * 32 + T - 1) / T, T>>>(b2, out, M);
}